// round 2
// baseline (speedup 1.0000x reference)
#include <cuda_runtime.h>
#include <math.h>

// Problem constants
#define cB 2
#define cL 12
#define cN 1024
#define cD 768
#define cM 3072
#define cH 12
#define cHD 64
#define cR (cB*cN)          // 2048 rows per block-call GEMM
#define RD (cR*cD)          // 2048*768
#define LRD (cL*cR*cD)

// ---------------- scratch (device globals; no allocation allowed) ----------
__device__ float g_pos[LRD];
__device__ float g_x  [LRD];
__device__ float g_yf [LRD];
__device__ float g_yb [LRD];
__device__ float g_h  [RD];
__device__ float g_hin[RD];
__device__ float g_xn [RD];
__device__ float g_hn [RD];
__device__ float g_qkv[cR*3*cD];
__device__ float g_kvp[8*cB*cH*cHD*cHD];   // partial kv sums: [chunk][bh][64][64]
__device__ float g_o  [RD];
__device__ float g_x2 [RD];
__device__ float g_x2n[RD];
__device__ float g_mlp[cR*cM];

// ---------------- helpers ---------------------------------------------------
__device__ __forceinline__ float geluf(float v){
    return 0.5f*v*(1.0f + erff(v*0.70710678118654752440f));
}

// ---------------- GEMM: C[2048 x Ncols] = A[2048 x K] @ W[K x Ncols] --------
// EPI 0: C = acc + bias + bias2              (qkv pass 1, both biases folded)
// EPI 1: C += acc                            (qkv pass 2 accumulate)
// EPI 2: v=acc+bias; C=v+res1; out2=v+res2   (attn: x2 and h_next)
// EPI 3: C = gelu(acc + bias)                (MLP up)
// EPI 4: C = acc + bias + res1               (MLP down + residual)
#define BM 128
#define BN 128
#define BK 16

template<int EPI>
__global__ __launch_bounds__(256) void k_gemm(
    const float* __restrict__ A, const float* __restrict__ W,
    float* __restrict__ C, int K, int Ncols,
    const float* __restrict__ bias, const float* __restrict__ bias2,
    const float* __restrict__ res1, float* __restrict__ out2,
    const float* __restrict__ res2)
{
    __shared__ float As[BK][BM];
    __shared__ float Bs[BK][BN];
    const int tid = threadIdx.x;
    const int tx = tid & 15, ty = tid >> 4;
    const float* Ab = A + (size_t)blockIdx.y * BM * K;
    const float* Wb = W + (size_t)blockIdx.x * BN;

    float acc[8][8];
    #pragma unroll
    for (int i=0;i<8;i++)
        #pragma unroll
        for (int j=0;j<8;j++) acc[i][j]=0.f;

    const int aRow = tid >> 2;
    const int aCol = (tid & 3) << 2;
    const int bRow = tid >> 5;
    const int bCol = (tid & 31) << 2;

    for (int k0 = 0; k0 < K; k0 += BK) {
        #pragma unroll
        for (int i=0;i<2;i++){
            int r = aRow + i*64;
            float4 v = *(const float4*)(Ab + (size_t)r*K + k0 + aCol);
            As[aCol+0][r]=v.x; As[aCol+1][r]=v.y; As[aCol+2][r]=v.z; As[aCol+3][r]=v.w;
        }
        #pragma unroll
        for (int i=0;i<2;i++){
            int r = bRow + i*8;
            *(float4*)(&Bs[r][bCol]) = *(const float4*)(Wb + (size_t)(k0+r)*Ncols + bCol);
        }
        __syncthreads();
        #pragma unroll
        for (int k=0;k<BK;k++){
            float a[8], b[8];
            *(float4*)(a)   = *(const float4*)(&As[k][ty*8]);
            *(float4*)(a+4) = *(const float4*)(&As[k][ty*8+4]);
            *(float4*)(b)   = *(const float4*)(&Bs[k][tx*8]);
            *(float4*)(b+4) = *(const float4*)(&Bs[k][tx*8+4]);
            #pragma unroll
            for (int i=0;i<8;i++)
                #pragma unroll
                for (int j=0;j<8;j++)
                    acc[i][j] = fmaf(a[i], b[j], acc[i][j]);
        }
        __syncthreads();
    }

    const int row0 = blockIdx.y*BM + ty*8;
    const int col0 = blockIdx.x*BN + tx*8;
    #pragma unroll
    for (int i=0;i<8;i++){
        int row = row0 + i;
        #pragma unroll
        for (int j=0;j<8;j++){
            int col = col0 + j;
            size_t idx = (size_t)row*Ncols + col;
            float v = acc[i][j];
            if (EPI == 0)       { v += bias[col] + bias2[col]; C[idx] = v; }
            else if (EPI == 1)  { C[idx] += v; }
            else if (EPI == 2)  { v += bias[col]; C[idx] = v + res1[idx]; out2[idx] = v + res2[idx]; }
            else if (EPI == 3)  { v += bias[col]; C[idx] = geluf(v); }
            else                { v += bias[col] + res1[idx]; C[idx] = v; }
        }
    }
}

// ---------------- LayerNorm: one block per row; optional add input;
// writes normalized (outn) and optionally the raw sum (outs) ----------------
__global__ __launch_bounds__(256) void k_ln(
    const float* __restrict__ in, const float* __restrict__ add,
    const float* __restrict__ gma, const float* __restrict__ bta,
    float* __restrict__ outn, float* __restrict__ outs)
{
    __shared__ float sh[8];
    __shared__ float s_m, s_r;
    const int r = blockIdx.x, t = threadIdx.x;
    const int lane = t & 31, w = t >> 5;
    const size_t base = (size_t)r*cD;
    const float* row = in + base;
    float v0 = row[t], v1 = row[t+256], v2 = row[t+512];
    if (add){
        const float* ar = add + base;
        v0 += ar[t]; v1 += ar[t+256]; v2 += ar[t+512];
    }
    float s = v0+v1+v2;
    #pragma unroll
    for (int o=16;o>0;o>>=1) s += __shfl_down_sync(0xffffffffu, s, o);
    if (lane==0) sh[w]=s;
    __syncthreads();
    if (t==0){ float tot=0.f; for (int i=0;i<8;i++) tot+=sh[i]; s_m = tot*(1.f/cD); }
    __syncthreads();
    const float m = s_m;
    float d0=v0-m, d1=v1-m, d2=v2-m;
    float q = d0*d0 + d1*d1 + d2*d2;
    #pragma unroll
    for (int o=16;o>0;o>>=1) q += __shfl_down_sync(0xffffffffu, q, o);
    if (lane==0) sh[w]=q;
    __syncthreads();
    if (t==0){ float tot=0.f; for (int i=0;i<8;i++) tot+=sh[i]; s_r = rsqrtf(tot*(1.f/cD) + 1e-5f); }
    __syncthreads();
    const float rs = s_r;
    outn[base+t]     = d0*rs*gma[t]     + bta[t];
    outn[base+t+256] = d1*rs*gma[t+256] + bta[t+256];
    outn[base+t+512] = d2*rs*gma[t+512] + bta[t+512];
    if (outs){ outs[base+t]=v0; outs[base+t+256]=v1; outs[base+t+512]=v2; }
}

// ---------------- elementwise kernels --------------------------------------
__global__ void k_pos_init(const float* __restrict__ x_in,
                           const float* __restrict__ spat,
                           const float* __restrict__ temp)
{
    const int D4 = cD/4;
    const int tot = cL*cR*D4;
    int idx = blockIdx.x*blockDim.x + threadIdx.x;
    if (idx >= tot) return;
    int d4 = idx % D4;
    int r  = (idx / D4) % cR;
    int l  = idx / (D4*cR);
    int b = r >> 10, n = r & (cN-1);
    float4 tp = ((const float4*)temp)[(size_t)(b*cL + l)*D4 + d4];
    float4 sp = ((const float4*)spat)[(size_t)r*D4 + d4];
    float4 xi = ((const float4*)x_in)[((size_t)(b*cL + l)*cN + n)*D4 + d4];
    float4 p, xo;
    p.x=tp.x*sp.x; p.y=tp.y*sp.y; p.z=tp.z*sp.z; p.w=tp.w*sp.w;
    xo.x=xi.x+p.x; xo.y=xi.y+p.y; xo.z=xi.z+p.z; xo.w=xi.w+p.w;
    ((float4*)g_pos)[idx] = p;
    ((float4*)g_x)[idx]   = xo;
}

__global__ void k_combine()
{
    const int tot = LRD/4;
    int idx = blockIdx.x*blockDim.x + threadIdx.x;
    if (idx >= tot) return;
    float4 a = ((const float4*)g_yf)[idx];
    float4 c = ((const float4*)g_yb)[idx];
    float4 p = ((const float4*)g_pos)[idx];
    float4 o;
    o.x=a.x+c.x+p.x; o.y=a.y+c.y+p.y; o.z=a.z+c.z+p.z; o.w=a.w+c.w+p.w;
    ((float4*)g_x)[idx] = o;
}

__global__ void k_out(float* __restrict__ out)
{
    const int D4 = cD/4;
    const int tot = cL*cR*D4;
    int idx = blockIdx.x*blockDim.x + threadIdx.x;
    if (idx >= tot) return;
    int d4 = idx % D4;
    int r  = (idx / D4) % cR;
    int l  = idx / (D4*cR);
    int b = r >> 10, n = r & (cN-1);
    float4 a = ((const float4*)g_yf)[idx];
    float4 c = ((const float4*)g_yb)[idx];
    float4 o;
    o.x=a.x+c.x; o.y=a.y+c.y; o.z=a.z+c.z; o.w=a.w+c.w;
    ((float4*)out)[((size_t)(b*cL + l)*cN + n)*D4 + d4] = o;
}

__global__ void k_seth(const float* __restrict__ hid)
{
    const int tot = RD/4;
    int idx = blockIdx.x*blockDim.x + threadIdx.x;
    if (idx >= tot) return;
    ((float4*)g_h)[idx] = ((const float4*)hid)[idx];
}

// elu(x)+1 applied in-place to q,k segments (cols 0..1535) of g_qkv
__global__ void k_elu()
{
    const int C4 = 2*cD/4;   // 384 float4 per row
    const int tot = cR*C4;
    int idx = blockIdx.x*blockDim.x + threadIdx.x;
    if (idx >= tot) return;
    int r = idx / C4, c4 = idx % C4;
    float4* p = ((float4*)g_qkv) + (size_t)r*(3*cD/4) + c4;
    float4 v = *p;
    v.x = (v.x > 0.f) ? v.x + 1.f : expf(v.x);
    v.y = (v.y > 0.f) ? v.y + 1.f : expf(v.y);
    v.z = (v.z > 0.f) ? v.z + 1.f : expf(v.z);
    v.w = (v.w > 0.f) ? v.w + 1.f : expf(v.w);
    *p = v;
}

// kv partial: per (b,h) and j-chunk of 128: kv[d][e] = sum_j K[j][d]*V[j][e]
__global__ __launch_bounds__(256) void k_kv()
{
    int bh = blockIdx.x;       // 0..23
    int chunk = blockIdx.y;    // 0..7
    int b = bh / cH, h = bh % cH;
    __shared__ float Ks[32][64];
    __shared__ float Vs[32][64];
    float acc[4][4];
    #pragma unroll
    for (int i=0;i<4;i++)
        #pragma unroll
        for (int j=0;j<4;j++) acc[i][j]=0.f;
    const int tx = threadIdx.x & 15, ty = threadIdx.x >> 4;
    const int j0 = chunk*128;
    for (int jj=0; jj<128; jj+=32){
        #pragma unroll
        for (int i=0;i<2;i++){
            int e = threadIdx.x + i*256;
            int row = e >> 4, c4 = e & 15;
            size_t rbase = ((size_t)(b*cN + j0 + jj + row))*(3*cD);
            *(float4*)(&Ks[row][c4*4]) = *(const float4*)(g_qkv + rbase +   cD + h*cHD + c4*4);
            *(float4*)(&Vs[row][c4*4]) = *(const float4*)(g_qkv + rbase + 2*cD + h*cHD + c4*4);
        }
        __syncthreads();
        #pragma unroll
        for (int j=0;j<32;j++){
            float a[4], bb[4];
            #pragma unroll
            for (int i=0;i<4;i++){ a[i]=Ks[j][ty*4+i]; bb[i]=Vs[j][tx*4+i]; }
            #pragma unroll
            for (int i=0;i<4;i++)
                #pragma unroll
                for (int jj2=0;jj2<4;jj2++)
                    acc[i][jj2] = fmaf(a[i], bb[jj2], acc[i][jj2]);
        }
        __syncthreads();
    }
    float* outp = g_kvp + ((size_t)(chunk*(cB*cH) + bh))*(cHD*cHD);
    #pragma unroll
    for (int i=0;i<4;i++)
        #pragma unroll
        for (int j=0;j<4;j++)
            outp[(ty*4+i)*cHD + tx*4+j] = acc[i][j];
}

// o[n][e] = sum_d q[n][d] * kv[d][e]; reduces the 8 kv partials on load
__global__ __launch_bounds__(256) void k_o()
{
    int bh = blockIdx.x;   // 24
    int nt = blockIdx.y;   // 16 tiles of 64 rows
    int b = bh / cH, h = bh % cH;
    __shared__ float QsT[64][65];
    __shared__ float KVs[64][64];
    #pragma unroll
    for (int i=0;i<4;i++){
        int e4 = threadIdx.x + i*256;
        float4 s = make_float4(0.f,0.f,0.f,0.f);
        #pragma unroll
        for (int c=0;c<8;c++){
            float4 p = ((const float4*)(g_kvp + ((size_t)(c*(cB*cH)+bh))*(cHD*cHD)))[e4];
            s.x+=p.x; s.y+=p.y; s.z+=p.z; s.w+=p.w;
        }
        ((float4*)KVs)[e4] = s;
    }
    #pragma unroll
    for (int i=0;i<4;i++){
        int e4 = threadIdx.x + i*256;
        int row = e4 >> 4, c4 = e4 & 15;
        int n = nt*64 + row;
        float4 q4 = *(const float4*)(g_qkv + ((size_t)(b*cN + n))*(3*cD) + h*cHD + c4*4);
        QsT[c4*4+0][row]=q4.x; QsT[c4*4+1][row]=q4.y; QsT[c4*4+2][row]=q4.z; QsT[c4*4+3][row]=q4.w;
    }
    __syncthreads();
    const int tx = threadIdx.x & 15, ty = threadIdx.x >> 4;
    float acc[4][4];
    #pragma unroll
    for (int i=0;i<4;i++)
        #pragma unroll
        for (int j=0;j<4;j++) acc[i][j]=0.f;
    for (int d=0; d<64; d++){
        float a[4], bb[4];
        #pragma unroll
        for (int i=0;i<4;i++){ a[i]=QsT[d][ty*4+i]; bb[i]=KVs[d][tx*4+i]; }
        #pragma unroll
        for (int i=0;i<4;i++)
            #pragma unroll
            for (int j=0;j<4;j++)
                acc[i][j] = fmaf(a[i], bb[j], acc[i][j]);
    }
    #pragma unroll
    for (int i=0;i<4;i++){
        int n = nt*64 + ty*4 + i;
        #pragma unroll
        for (int j=0;j<4;j++)
            g_o[((size_t)(b*cN+n))*cD + h*cHD + tx*4 + j] = acc[i][j];
    }
}

// ---------------- driver ----------------------------------------------------
extern "C" void kernel_launch(void* const* d_in, const int* in_sizes, int n_in,
                              void* d_out, int out_size)
{
    (void)in_sizes; (void)n_in; (void)out_size;
    const float* x_in  = (const float*)d_in[0];
    const float* hid   = (const float*)d_in[1];
    const float* spat  = (const float*)d_in[2];
    const float* temp  = (const float*)d_in[3];
    const float* lni_g = (const float*)d_in[4];
    const float* lni_b = (const float*)d_in[5];
    const float* lnh_g = (const float*)d_in[6];
    const float* lnh_b = (const float*)d_in[7];
    const float* lno_g = (const float*)d_in[8];
    const float* lno_b = (const float*)d_in[9];
    const float* Wqkv  = (const float*)d_in[10];
    const float* bqkv  = (const float*)d_in[11];
    const float* Wqkvh = (const float*)d_in[12];
    const float* bqkvh = (const float*)d_in[13];
    const float* Wout  = (const float*)d_in[14];
    const float* bout  = (const float*)d_in[15];
    const float* W1    = (const float*)d_in[16];
    const float* b1    = (const float*)d_in[17];
    const float* W2    = (const float*)d_in[18];
    const float* b2    = (const float*)d_in[19];

    float *p_pos,*p_x,*p_yf,*p_yb,*p_h,*p_hin,*p_xn,*p_hn,*p_qkv,*p_o,*p_x2,*p_x2n,*p_mlp;
    cudaGetSymbolAddress((void**)&p_pos, g_pos);
    cudaGetSymbolAddress((void**)&p_x,   g_x);
    cudaGetSymbolAddress((void**)&p_yf,  g_yf);
    cudaGetSymbolAddress((void**)&p_yb,  g_yb);
    cudaGetSymbolAddress((void**)&p_h,   g_h);
    cudaGetSymbolAddress((void**)&p_hin, g_hin);
    cudaGetSymbolAddress((void**)&p_xn,  g_xn);
    cudaGetSymbolAddress((void**)&p_hn,  g_hn);
    cudaGetSymbolAddress((void**)&p_qkv, g_qkv);
    cudaGetSymbolAddress((void**)&p_o,   g_o);
    cudaGetSymbolAddress((void**)&p_x2,  g_x2);
    cudaGetSymbolAddress((void**)&p_x2n, g_x2n);
    cudaGetSymbolAddress((void**)&p_mlp, g_mlp);

    const int EW = 256;
    const int tot4 = LRD/4;
    k_pos_init<<<(tot4+EW-1)/EW, EW>>>(x_in, spat, temp);

    for (int layer=0; layer<2; layer++){
        if (layer) k_combine<<<(tot4+EW-1)/EW, EW>>>();
        for (int dir=0; dir<2; dir++){
            int sel = dir*2 + layer;                 // params[dir][layer]
            k_seth<<<(RD/4+EW-1)/EW, EW>>>(hid);
            for (int s=0; s<cL; s++){
                int t  = (dir==0) ? s : (cL-1-s);
                int pl = (dir==0) ? layer : t;       // fwd: pos[:,layer]; bwd: pos[:,t]
                const float* xt = p_x + (size_t)t*RD;
                float*       yt = ((dir==0) ? p_yf : p_yb) + (size_t)t*RD;

                // hn = LN(h + pos_sel), also store hin = h + pos_sel
                k_ln<<<cR,256>>>(p_h, p_pos + (size_t)pl*RD,
                                 lnh_g + (size_t)sel*cD, lnh_b + (size_t)sel*cD,
                                 p_hn, p_hin);
                // xn = LN(x_t)
                k_ln<<<cR,256>>>(xt, (const float*)nullptr,
                                 lni_g + (size_t)sel*cD, lni_b + (size_t)sel*cD,
                                 p_xn, (float*)nullptr);
                // qkv = xn@Wqkv + (bqkv+bqkvh)
                k_gemm<0><<<dim3(3*cD/BN, cR/BM),256>>>(
                    p_xn, Wqkv + (size_t)sel*cD*3*cD, p_qkv, cD, 3*cD,
                    bqkv + (size_t)sel*3*cD, bqkvh + (size_t)sel*3*cD,
                    nullptr, nullptr, nullptr);
                // qkv += hn@Wqkvh
                k_gemm<1><<<dim3(3*cD/BN, cR/BM),256>>>(
                    p_hn, Wqkvh + (size_t)sel*cD*3*cD, p_qkv, cD, 3*cD,
                    nullptr, nullptr, nullptr, nullptr, nullptr);
                // q,k <- elu+1
                k_elu<<<(cR*2*cD/4+EW-1)/EW, EW>>>();
                // kv partials, then o = q @ kv
                k_kv<<<dim3(cB*cH, 8),256>>>();
                k_o <<<dim3(cB*cH, cN/64),256>>>();
                // attn = o@Wout + bout; x2 = attn + x; h = attn + hin
                k_gemm<2><<<dim3(cD/BN, cR/BM),256>>>(
                    p_o, Wout + (size_t)sel*cD*cD, p_x2, cD, cD,
                    bout + (size_t)sel*cD, nullptr, xt, p_h, p_hin);
                // x2n = LN(x2)
                k_ln<<<cR,256>>>(p_x2, (const float*)nullptr,
                                 lno_g + (size_t)sel*cD, lno_b + (size_t)sel*cD,
                                 p_x2n, (float*)nullptr);
                // mlp = gelu(x2n@W1 + b1)
                k_gemm<3><<<dim3(cM/BN, cR/BM),256>>>(
                    p_x2n, W1 + (size_t)sel*cD*cM, p_mlp, cD, cM,
                    b1 + (size_t)sel*cM, nullptr, nullptr, nullptr, nullptr);
                // y_t = mlp@W2 + b2 + x2
                k_gemm<4><<<dim3(cD/BN, cR/BM),256>>>(
                    p_mlp, W2 + (size_t)sel*cM*cD, yt, cM, cD,
                    b2 + (size_t)sel*cD, nullptr, p_x2, nullptr, nullptr);
            }
        }
    }
    k_out<<<(tot4+EW-1)/EW, EW>>>((float*)d_out);
}

// round 7
// speedup vs baseline: 3.7304x; 3.7304x over previous
#include <cuda_runtime.h>
#include <math.h>
#include <stdint.h>

// Problem constants
#define cB 2
#define cL 12
#define cN 1024
#define cD 768
#define cM 3072
#define cH 12
#define cHD 64
#define cR (cB*cN)          // 2048 rows per step
#define RD (cR*cD)
#define LRD (cL*cR*cD)

// ---------------- scratch (device globals; no allocation allowed) ----------
__device__ float g_pos [LRD];
__device__ float g_x   [LRD];
__device__ float g_yf  [LRD];
__device__ float g_yb  [LRD];
__device__ float g_xn  [LRD];                 // batched LN(x) for all t
__device__ float g_qkvx[(size_t)cL*cR*3*cD];  // batched xn@Wqkv (+biases)
__device__ float g_x2  [LRD];                 // x2 for all t
__device__ float g_x2n [LRD];
__device__ float g_mlp [(size_t)cL*cR*cM];
__device__ float g_h   [RD];
__device__ float g_hin [RD];
__device__ float g_hn  [RD];
__device__ float g_qkv [cR*3*cD];
__device__ float g_kvp [8*cB*cH*cHD*cHD];
__device__ float g_o   [RD];

// ---------------- helpers ---------------------------------------------------
__device__ __forceinline__ float geluf(float v){
    return 0.5f*v*(1.0f + erff(v*0.70710678118654752440f));
}
__device__ __forceinline__ uint32_t f2tf(float x){
    uint32_t r; asm("cvt.rna.tf32.f32 %0, %1;" : "=r"(r) : "f"(x)); return r;
}
__device__ __forceinline__ void mma_tf32(float* c, const uint32_t* a, const uint32_t* b){
    asm volatile("mma.sync.aligned.m16n8k8.row.col.f32.tf32.tf32.f32 "
        "{%0,%1,%2,%3}, {%4,%5,%6,%7}, {%8,%9}, {%0,%1,%2,%3};"
        : "+f"(c[0]), "+f"(c[1]), "+f"(c[2]), "+f"(c[3])
        : "r"(a[0]), "r"(a[1]), "r"(a[2]), "r"(a[3]), "r"(b[0]), "r"(b[1]));
}
__device__ __forceinline__ void cp16(void* sdst, const void* gsrc){
    uint32_t s = (uint32_t)__cvta_generic_to_shared(sdst);
    asm volatile("cp.async.cg.shared.global [%0], [%1], 16;" :: "r"(s), "l"(gsrc));
}

// ---------------- TF32 tensor-core GEMM ------------------------------------
// C[M x Ncols] = A[M x K] @ W[K x Ncols], M%128==0, Ncols%128==0, K%32==0.
// Block 128x128, K-tile 32, 256 threads = 8 warps (2 m x 4 n), warp tile 64x32,
// per-warp mma grid 4(m16) x 4(n8), cp.async double buffered.
// EPI 0: C = acc + bias[col] + bias2[col]                    (batched qkv_x)
// EPI 2: v = acc + bias; C = v + aux1; out2 = v + aux2       (attn out)
// EPI 3: C = gelu(acc + bias)                                (MLP up)
// EPI 4: C = acc + bias + aux1[idx]                          (MLP down + res)
// EPI 5: v = acc + aux1[idx]; C = col<1536 ? elu(v)+1 : v    (qkv_h + elu)
#define ASTRIDE 36
#define BSTRIDE 136
#define SMEM_BYTES ((2*128*ASTRIDE + 2*32*BSTRIDE)*4)

template<int EPI>
__global__ __launch_bounds__(256) void k_tgemm(
    const float* __restrict__ A, const float* __restrict__ W,
    float* __restrict__ C, int K, int Ncols,
    const float* __restrict__ bias, const float* __restrict__ bias2,
    const float* __restrict__ aux1, float* __restrict__ out2,
    const float* __restrict__ aux2)
{
    extern __shared__ float smem[];
    float* As = smem;                      // [2][128][ASTRIDE]
    float* Bs = smem + 2*128*ASTRIDE;      // [2][32][BSTRIDE]

    const int tid  = threadIdx.x;
    const int warp = tid >> 5, lane = tid & 31;
    const int wm = (warp & 1) * 64;
    const int wn = (warp >> 1) * 32;
    const int g  = lane >> 2, t4 = lane & 3;

    const float* Ab = A + (size_t)blockIdx.y * 128 * K;
    const float* Wb = W + (size_t)blockIdx.x * 128;

    float acc[4][4][4];
    #pragma unroll
    for (int i=0;i<4;i++)
        #pragma unroll
        for (int j=0;j<4;j++)
            #pragma unroll
            for (int e=0;e<4;e++) acc[i][j][e] = 0.f;

    const int KT = K >> 5;

    // stage loader
    auto load_tile = [&](int kt, int buf){
        float* Asl = As + buf*(128*ASTRIDE);
        float* Bsl = Bs + buf*(32*BSTRIDE);
        #pragma unroll
        for (int r=0;r<4;r++){
            int c   = tid + 256*r;
            int row = c >> 3;
            int kc  = (c & 7) << 2;
            cp16(Asl + row*ASTRIDE + kc, Ab + (size_t)row*K + kt*32 + kc);
        }
        #pragma unroll
        for (int r=0;r<4;r++){
            int c   = tid + 256*r;
            int row = c >> 5;
            int nc  = (c & 31) << 2;
            cp16(Bsl + row*BSTRIDE + nc, Wb + (size_t)(kt*32+row)*Ncols + nc);
        }
        asm volatile("cp.async.commit_group;");
    };

    load_tile(0, 0);

    for (int kt = 0; kt < KT; kt++){
        if (kt + 1 < KT){
            load_tile(kt+1, (kt+1)&1);
            asm volatile("cp.async.wait_group 1;");
        } else {
            asm volatile("cp.async.wait_group 0;");
        }
        __syncthreads();

        const float* Asb = As + (kt&1)*(128*ASTRIDE);
        const float* Bsb = Bs + (kt&1)*(32*BSTRIDE);
        #pragma unroll
        for (int kk=0; kk<4; kk++){
            uint32_t af[4][4], bf[4][2];
            #pragma unroll
            for (int i=0;i<4;i++){
                int r0 = wm + i*16 + g;
                af[i][0] = f2tf(Asb[(size_t)r0*ASTRIDE + kk*8 + t4]);
                af[i][1] = f2tf(Asb[(size_t)(r0+8)*ASTRIDE + kk*8 + t4]);
                af[i][2] = f2tf(Asb[(size_t)r0*ASTRIDE + kk*8 + t4 + 4]);
                af[i][3] = f2tf(Asb[(size_t)(r0+8)*ASTRIDE + kk*8 + t4 + 4]);
            }
            #pragma unroll
            for (int j=0;j<4;j++){
                bf[j][0] = f2tf(Bsb[(size_t)(kk*8+t4)*BSTRIDE + wn + j*8 + g]);
                bf[j][1] = f2tf(Bsb[(size_t)(kk*8+t4+4)*BSTRIDE + wn + j*8 + g]);
            }
            #pragma unroll
            for (int i=0;i<4;i++)
                #pragma unroll
                for (int j=0;j<4;j++)
                    mma_tf32(acc[i][j], af[i], bf[j]);
        }
        __syncthreads();
    }

    // epilogue
    const int row_base = blockIdx.y*128 + wm;
    const int col_base = blockIdx.x*128 + wn;
    #pragma unroll
    for (int i=0;i<4;i++){
        #pragma unroll
        for (int j=0;j<4;j++){
            int c0 = col_base + j*8 + t4*2;
            #pragma unroll
            for (int e=0;e<4;e++){
                int row = row_base + i*16 + g + ((e>>1)?8:0);
                int col = c0 + (e&1);
                size_t idx = (size_t)row*Ncols + col;
                float v = acc[i][j][e];
                if (EPI == 0){
                    C[idx] = v + bias[col] + bias2[col];
                } else if (EPI == 2){
                    float t = v + bias[col];
                    C[idx]    = t + aux1[idx];
                    out2[idx] = t + aux2[idx];
                } else if (EPI == 3){
                    C[idx] = geluf(v + bias[col]);
                } else if (EPI == 4){
                    C[idx] = v + bias[col] + aux1[idx];
                } else { // 5
                    float t = v + aux1[idx];
                    if (col < 2*cD) t = (t > 0.f) ? t + 1.f : expf(t);
                    C[idx] = t;
                }
            }
        }
    }
}

// ---------------- LayerNorm ------------------------------------------------
__global__ __launch_bounds__(256) void k_ln(
    const float* __restrict__ in, const float* __restrict__ add,
    const float* __restrict__ gma, const float* __restrict__ bta,
    float* __restrict__ outn, float* __restrict__ outs)
{
    __shared__ float sh[8];
    __shared__ float s_m, s_r;
    const int r = blockIdx.x, t = threadIdx.x;
    const int lane = t & 31, w = t >> 5;
    const size_t base = (size_t)r*cD;
    const float* row = in + base;
    float v0 = row[t], v1 = row[t+256], v2 = row[t+512];
    if (add){
        const float* ar = add + base;
        v0 += ar[t]; v1 += ar[t+256]; v2 += ar[t+512];
    }
    float s = v0+v1+v2;
    #pragma unroll
    for (int o=16;o>0;o>>=1) s += __shfl_down_sync(0xffffffffu, s, o);
    if (lane==0) sh[w]=s;
    __syncthreads();
    if (t==0){ float tot=0.f; for (int i=0;i<8;i++) tot+=sh[i]; s_m = tot*(1.f/cD); }
    __syncthreads();
    const float m = s_m;
    float d0=v0-m, d1=v1-m, d2=v2-m;
    float q = d0*d0 + d1*d1 + d2*d2;
    #pragma unroll
    for (int o=16;o>0;o>>=1) q += __shfl_down_sync(0xffffffffu, q, o);
    if (lane==0) sh[w]=q;
    __syncthreads();
    if (t==0){ float tot=0.f; for (int i=0;i<8;i++) tot+=sh[i]; s_r = rsqrtf(tot*(1.f/cD) + 1e-5f); }
    __syncthreads();
    const float rs = s_r;
    outn[base+t]     = d0*rs*gma[t]     + bta[t];
    outn[base+t+256] = d1*rs*gma[t+256] + bta[t+256];
    outn[base+t+512] = d2*rs*gma[t+512] + bta[t+512];
    if (outs){ outs[base+t]=v0; outs[base+t+256]=v1; outs[base+t+512]=v2; }
}

// ---------------- elementwise kernels --------------------------------------
__global__ void k_pos_init(const float* __restrict__ x_in,
                           const float* __restrict__ spat,
                           const float* __restrict__ temp)
{
    const int D4 = cD/4;
    const int tot = cL*cR*D4;
    int idx = blockIdx.x*blockDim.x + threadIdx.x;
    if (idx >= tot) return;
    int d4 = idx % D4;
    int r  = (idx / D4) % cR;
    int l  = idx / (D4*cR);
    int b = r >> 10, n = r & (cN-1);
    float4 tp = ((const float4*)temp)[(size_t)(b*cL + l)*D4 + d4];
    float4 sp = ((const float4*)spat)[(size_t)r*D4 + d4];
    float4 xi = ((const float4*)x_in)[((size_t)(b*cL + l)*cN + n)*D4 + d4];
    float4 p, xo;
    p.x=tp.x*sp.x; p.y=tp.y*sp.y; p.z=tp.z*sp.z; p.w=tp.w*sp.w;
    xo.x=xi.x+p.x; xo.y=xi.y+p.y; xo.z=xi.z+p.z; xo.w=xi.w+p.w;
    ((float4*)g_pos)[idx] = p;
    ((float4*)g_x)[idx]   = xo;
}

__global__ void k_combine()
{
    const int tot = LRD/4;
    int idx = blockIdx.x*blockDim.x + threadIdx.x;
    if (idx >= tot) return;
    float4 a = ((const float4*)g_yf)[idx];
    float4 c = ((const float4*)g_yb)[idx];
    float4 p = ((const float4*)g_pos)[idx];
    float4 o;
    o.x=a.x+c.x+p.x; o.y=a.y+c.y+p.y; o.z=a.z+c.z+p.z; o.w=a.w+c.w+p.w;
    ((float4*)g_x)[idx] = o;
}

__global__ void k_out(float* __restrict__ out)
{
    const int D4 = cD/4;
    const int tot = cL*cR*D4;
    int idx = blockIdx.x*blockDim.x + threadIdx.x;
    if (idx >= tot) return;
    int d4 = idx % D4;
    int r  = (idx / D4) % cR;
    int l  = idx / (D4*cR);
    int b = r >> 10, n = r & (cN-1);
    float4 a = ((const float4*)g_yf)[idx];
    float4 c = ((const float4*)g_yb)[idx];
    float4 o;
    o.x=a.x+c.x; o.y=a.y+c.y; o.z=a.z+c.z; o.w=a.w+c.w;
    ((float4*)out)[((size_t)(b*cL + l)*cN + n)*D4 + d4] = o;
}

__global__ void k_seth(const float* __restrict__ hid)
{
    const int tot = RD/4;
    int idx = blockIdx.x*blockDim.x + threadIdx.x;
    if (idx >= tot) return;
    ((float4*)g_h)[idx] = ((const float4*)hid)[idx];
}

// kv partial: per (b,h) and j-chunk of 128: kv[d][e] = sum_j K[j][d]*V[j][e]
__global__ __launch_bounds__(256) void k_kv()
{
    int bh = blockIdx.x;
    int chunk = blockIdx.y;
    int b = bh / cH, h = bh % cH;
    __shared__ float Ks[32][64];
    __shared__ float Vs[32][64];
    float acc[4][4];
    #pragma unroll
    for (int i=0;i<4;i++)
        #pragma unroll
        for (int j=0;j<4;j++) acc[i][j]=0.f;
    const int tx = threadIdx.x & 15, ty = threadIdx.x >> 4;
    const int j0 = chunk*128;
    for (int jj=0; jj<128; jj+=32){
        #pragma unroll
        for (int i=0;i<2;i++){
            int e = threadIdx.x + i*256;
            int row = e >> 4, c4 = e & 15;
            size_t rbase = ((size_t)(b*cN + j0 + jj + row))*(3*cD);
            *(float4*)(&Ks[row][c4*4]) = *(const float4*)(g_qkv + rbase +   cD + h*cHD + c4*4);
            *(float4*)(&Vs[row][c4*4]) = *(const float4*)(g_qkv + rbase + 2*cD + h*cHD + c4*4);
        }
        __syncthreads();
        #pragma unroll
        for (int j=0;j<32;j++){
            float a[4], bb[4];
            #pragma unroll
            for (int i=0;i<4;i++){ a[i]=Ks[j][ty*4+i]; bb[i]=Vs[j][tx*4+i]; }
            #pragma unroll
            for (int i=0;i<4;i++)
                #pragma unroll
                for (int jj2=0;jj2<4;jj2++)
                    acc[i][jj2] = fmaf(a[i], bb[jj2], acc[i][jj2]);
        }
        __syncthreads();
    }
    float* outp = g_kvp + ((size_t)(chunk*(cB*cH) + bh))*(cHD*cHD);
    #pragma unroll
    for (int i=0;i<4;i++)
        #pragma unroll
        for (int j=0;j<4;j++)
            outp[(ty*4+i)*cHD + tx*4+j] = acc[i][j];
}

// o[n][e] = sum_d q[n][d] * kv[d][e]; reduces the 8 kv partials on load
__global__ __launch_bounds__(256) void k_o()
{
    int bh = blockIdx.x;
    int nt = blockIdx.y;
    int b = bh / cH, h = bh % cH;
    __shared__ float QsT[64][65];
    __shared__ float KVs[64][64];
    #pragma unroll
    for (int i=0;i<4;i++){
        int e4 = threadIdx.x + i*256;
        float4 s = make_float4(0.f,0.f,0.f,0.f);
        #pragma unroll
        for (int c=0;c<8;c++){
            float4 p = ((const float4*)(g_kvp + ((size_t)(c*(cB*cH)+bh))*(cHD*cHD)))[e4];
            s.x+=p.x; s.y+=p.y; s.z+=p.z; s.w+=p.w;
        }
        ((float4*)KVs)[e4] = s;
    }
    #pragma unroll
    for (int i=0;i<4;i++){
        int e4 = threadIdx.x + i*256;
        int row = e4 >> 4, c4 = e4 & 15;
        int n = nt*64 + row;
        float4 q4 = *(const float4*)(g_qkv + ((size_t)(b*cN + n))*(3*cD) + h*cHD + c4*4);
        QsT[c4*4+0][row]=q4.x; QsT[c4*4+1][row]=q4.y; QsT[c4*4+2][row]=q4.z; QsT[c4*4+3][row]=q4.w;
    }
    __syncthreads();
    const int tx = threadIdx.x & 15, ty = threadIdx.x >> 4;
    float acc[4][4];
    #pragma unroll
    for (int i=0;i<4;i++)
        #pragma unroll
        for (int j=0;j<4;j++) acc[i][j]=0.f;
    for (int d=0; d<64; d++){
        float a[4], bb[4];
        #pragma unroll
        for (int i=0;i<4;i++){ a[i]=QsT[d][ty*4+i]; bb[i]=KVs[d][tx*4+i]; }
        #pragma unroll
        for (int i=0;i<4;i++)
            #pragma unroll
            for (int j=0;j<4;j++)
                acc[i][j] = fmaf(a[i], bb[j], acc[i][j]);
    }
    #pragma unroll
    for (int i=0;i<4;i++){
        int n = nt*64 + ty*4 + i;
        #pragma unroll
        for (int j=0;j<4;j++)
            g_o[((size_t)(b*cN+n))*cD + h*cHD + tx*4 + j] = acc[i][j];
    }
}

// ---------------- driver ----------------------------------------------------
extern "C" void kernel_launch(void* const* d_in, const int* in_sizes, int n_in,
                              void* d_out, int out_size)
{
    (void)in_sizes; (void)n_in; (void)out_size;
    const float* x_in  = (const float*)d_in[0];
    const float* hid   = (const float*)d_in[1];
    const float* spat  = (const float*)d_in[2];
    const float* temp  = (const float*)d_in[3];
    const float* lni_g = (const float*)d_in[4];
    const float* lni_b = (const float*)d_in[5];
    const float* lnh_g = (const float*)d_in[6];
    const float* lnh_b = (const float*)d_in[7];
    const float* lno_g = (const float*)d_in[8];
    const float* lno_b = (const float*)d_in[9];
    const float* Wqkv  = (const float*)d_in[10];
    const float* bqkv  = (const float*)d_in[11];
    const float* Wqkvh = (const float*)d_in[12];
    const float* bqkvh = (const float*)d_in[13];
    const float* Wout  = (const float*)d_in[14];
    const float* bout  = (const float*)d_in[15];
    const float* W1    = (const float*)d_in[16];
    const float* b1    = (const float*)d_in[17];
    const float* W2    = (const float*)d_in[18];
    const float* b2    = (const float*)d_in[19];

    float *p_pos,*p_x,*p_yf,*p_yb,*p_xn,*p_qkvx,*p_x2,*p_x2n,*p_mlp;
    float *p_h,*p_hin,*p_hn,*p_qkv,*p_o;
    cudaGetSymbolAddress((void**)&p_pos,  g_pos);
    cudaGetSymbolAddress((void**)&p_x,    g_x);
    cudaGetSymbolAddress((void**)&p_yf,   g_yf);
    cudaGetSymbolAddress((void**)&p_yb,   g_yb);
    cudaGetSymbolAddress((void**)&p_xn,   g_xn);
    cudaGetSymbolAddress((void**)&p_qkvx, g_qkvx);
    cudaGetSymbolAddress((void**)&p_x2,   g_x2);
    cudaGetSymbolAddress((void**)&p_x2n,  g_x2n);
    cudaGetSymbolAddress((void**)&p_mlp,  g_mlp);
    cudaGetSymbolAddress((void**)&p_h,    g_h);
    cudaGetSymbolAddress((void**)&p_hin,  g_hin);
    cudaGetSymbolAddress((void**)&p_hn,   g_hn);
    cudaGetSymbolAddress((void**)&p_qkv,  g_qkv);
    cudaGetSymbolAddress((void**)&p_o,    g_o);

    cudaFuncSetAttribute(k_tgemm<0>, cudaFuncAttributeMaxDynamicSharedMemorySize, SMEM_BYTES);
    cudaFuncSetAttribute(k_tgemm<2>, cudaFuncAttributeMaxDynamicSharedMemorySize, SMEM_BYTES);
    cudaFuncSetAttribute(k_tgemm<3>, cudaFuncAttributeMaxDynamicSharedMemorySize, SMEM_BYTES);
    cudaFuncSetAttribute(k_tgemm<4>, cudaFuncAttributeMaxDynamicSharedMemorySize, SMEM_BYTES);
    cudaFuncSetAttribute(k_tgemm<5>, cudaFuncAttributeMaxDynamicSharedMemorySize, SMEM_BYTES);

    const int EW = 256;
    const int tot4 = LRD/4;
    k_pos_init<<<(tot4+EW-1)/EW, EW>>>(x_in, spat, temp);

    for (int layer=0; layer<2; layer++){
        if (layer) k_combine<<<(tot4+EW-1)/EW, EW>>>();
        for (int dir=0; dir<2; dir++){
            int sel = dir*2 + layer;                 // params[dir][layer]

            // Batched over all t: xn = LN(x_t), qkvx = xn@Wqkv + bqkv + bqkvh
            k_ln<<<cL*cR,256>>>(p_x, (const float*)nullptr,
                                lni_g + (size_t)sel*cD, lni_b + (size_t)sel*cD,
                                p_xn, (float*)nullptr);
            k_tgemm<0><<<dim3(3*cD/128, cL*cR/128), 256, SMEM_BYTES>>>(
                p_xn, Wqkv + (size_t)sel*cD*3*cD, p_qkvx, cD, 3*cD,
                bqkv + (size_t)sel*3*cD, bqkvh + (size_t)sel*3*cD,
                nullptr, nullptr, nullptr);

            k_seth<<<(RD/4+EW-1)/EW, EW>>>(hid);
            for (int s=0; s<cL; s++){
                int t  = (dir==0) ? s : (cL-1-s);
                int pl = (dir==0) ? layer : t;       // fwd: pos[:,layer]; bwd: pos[:,t]
                const float* xt = p_x + (size_t)t*RD;

                // hn = LN(h + pos_sel); hin = h + pos_sel
                k_ln<<<cR,256>>>(p_h, p_pos + (size_t)pl*RD,
                                 lnh_g + (size_t)sel*cD, lnh_b + (size_t)sel*cD,
                                 p_hn, p_hin);
                // qkv = qkvx_t + hn@Wqkvh, elu+1 on q,k columns
                k_tgemm<5><<<dim3(3*cD/128, cR/128), 256, SMEM_BYTES>>>(
                    p_hn, Wqkvh + (size_t)sel*cD*3*cD, p_qkv, cD, 3*cD,
                    nullptr, nullptr,
                    p_qkvx + (size_t)t*cR*3*cD, nullptr, nullptr);
                // attention einsums
                k_kv<<<dim3(cB*cH, 8),256>>>();
                k_o <<<dim3(cB*cH, cN/64),256>>>();
                // attn = o@Wout + bout; x2_t = attn + x_t; h = attn + hin
                k_tgemm<2><<<dim3(cD/128, cR/128), 256, SMEM_BYTES>>>(
                    p_o, Wout + (size_t)sel*cD*cD, p_x2 + (size_t)t*RD, cD, cD,
                    bout + (size_t)sel*cD, nullptr, xt, p_h, p_hin);
            }

            // Batched MLP over all t
            float* yall = (dir==0) ? p_yf : p_yb;
            k_ln<<<cL*cR,256>>>(p_x2, (const float*)nullptr,
                                lno_g + (size_t)sel*cD, lno_b + (size_t)sel*cD,
                                p_x2n, (float*)nullptr);
            k_tgemm<3><<<dim3(cM/128, cL*cR/128), 256, SMEM_BYTES>>>(
                p_x2n, W1 + (size_t)sel*cD*cM, p_mlp, cD, cM,
                b1 + (size_t)sel*cM, nullptr, nullptr, nullptr, nullptr);
            k_tgemm<4><<<dim3(cD/128, cL*cR/128), 256, SMEM_BYTES>>>(
                p_mlp, W2 + (size_t)sel*cM*cD, yall, cM, cD,
                b2 + (size_t)sel*cD, nullptr, p_x2, nullptr, nullptr);
        }
    }
    k_out<<<(tot4+EW-1)/EW, EW>>>((float*)d_out);
}